// round 1
// baseline (speedup 1.0000x reference)
#include <cuda_runtime.h>
#include <cuda_bf16.h>
#include <math.h>

// ---------------------------------------------------------------------------
// CSBrainLLMVQ: EEG conv stack + GN + GELU + DFT spectral branch + depthwise
// positional conv + VQ (argmin over codebook) + output projection.
//
// Key restructuring (exact math, fp32 throughout):
//   score[t,k] = 0.5*||cb_k||^2 - inp_b.cb_k - pe[t].G[k],  G = cb @ inp_w
//   out[t]     = code_out[idx[t]] + outp_b,   code_out = cb @ outp_w.T
// ---------------------------------------------------------------------------

#define BB   32
#define CHN  19
#define NPP  30
#define PSZ  200
#define RR   570          // CHN*NPP
#define TT   18240        // BB*RR
#define DMD  200
#define LLM  4096
#define KCB  4096
#define C25  25
#define W8   8
#define HTOT (BB*C25*RR*W8)   // 3,648,000
#define PETOT (TT*DMD)        // 3,648,000
#define NFREQ 101

// scratch (device globals: no allocation allowed)
__device__ float g_bufA[HTOT];
__device__ float g_bufB[HTOT];
__device__ float g_pe[PETOT];
__device__ float g_spec[TT*NFREQ];
__device__ float g_G[KCB*DMD];
__device__ float g_c0[KCB];
__device__ float g_cout[KCB*DMD];
__device__ int   g_idx[TT];
__device__ float g_mean[BB*5];
__device__ float g_rstd[BB*5];

__device__ __forceinline__ float gelu_exact(float v) {
    return 0.5f * v * (1.0f + erff(v * 0.70710678118654752f));
}

// ---------------------------------------------------------------------------
// conv1: [B,1,570,200] -> [B,25,570,8], kernel (1,49), stride (1,25), pad W 24
// ---------------------------------------------------------------------------
__global__ __launch_bounds__(256) void k_conv1(const float* __restrict__ x,
                                               const float* __restrict__ w,
                                               const float* __restrict__ bias) {
    int br = blockIdx.x;                 // b*570 + r
    int b = br / RR, r = br % RR;
    __shared__ float xs[PSZ];
    __shared__ float ws[C25 * 49];
    __shared__ float bs[C25];
    int t = threadIdx.x;
    if (t < PSZ) xs[t] = x[(size_t)br * PSZ + t];
    for (int i = t; i < C25 * 49; i += 256) ws[i] = w[i];
    if (t < C25) bs[t] = bias[t];
    __syncthreads();
    if (t < 200) {
        int oc = t >> 3, ow = t & 7;
        float acc = bs[oc];
        int base = ow * 25 - 24;
        #pragma unroll 7
        for (int k = 0; k < 49; k++) {
            int p = base + k;
            if (p >= 0 && p < PSZ) acc += xs[p] * ws[oc * 49 + k];
        }
        g_bufA[(((size_t)b * C25 + oc) * RR + r) * W8 + ow] = acc;
    }
}

// ---------------------------------------------------------------------------
// GroupNorm stats: 5 groups of 5 channels; per (b,g) over 5*570*8 = 22800
// ---------------------------------------------------------------------------
__global__ __launch_bounds__(256) void k_gnstats(const float* __restrict__ h) {
    int bg = blockIdx.x;           // b*5 + g
    int b = bg / 5, g = bg % 5;
    float s1 = 0.f, s2 = 0.f;
    const int per = RR * W8;       // 4560
    for (int i = threadIdx.x; i < 5 * per; i += 256) {
        int oc = g * 5 + i / per;
        int rw = i % per;
        float v = h[(size_t)(b * C25 + oc) * per + rw];
        s1 += v; s2 += v * v;
    }
    __shared__ float r1[256], r2[256];
    int t = threadIdx.x;
    r1[t] = s1; r2[t] = s2;
    __syncthreads();
    for (int s = 128; s > 0; s >>= 1) {
        if (t < s) { r1[t] += r1[t + s]; r2[t] += r2[t + s]; }
        __syncthreads();
    }
    if (t == 0) {
        float m = r1[0] / 22800.f;
        float var = r2[0] / 22800.f - m * m;
        g_mean[bg] = m;
        g_rstd[bg] = rsqrtf(var + 1e-5f);
    }
}

// apply GN (scale/bias per channel) + exact GELU, in place
__global__ __launch_bounds__(256) void k_gngelu(float* __restrict__ h,
                                                const float* __restrict__ sc,
                                                const float* __restrict__ bi) {
    int i = blockIdx.x * 256 + threadIdx.x;
    if (i >= HTOT) return;
    const int per = RR * W8;
    int b = i / (C25 * per);
    int oc = (i / per) % C25;
    int bg = b * 5 + oc / 5;
    float v = (h[i] - g_mean[bg]) * g_rstd[bg] * sc[oc] + bi[oc];
    h[i] = gelu_exact(v);
}

// ---------------------------------------------------------------------------
// conv2/conv3: [B,25,570,8] -> same, kernel (1,3), pad W 1
// ---------------------------------------------------------------------------
__global__ __launch_bounds__(256) void k_conv3x(const float* __restrict__ in,
                                                const float* __restrict__ w,
                                                const float* __restrict__ bias,
                                                float* __restrict__ out) {
    int bi = blockIdx.x;                // b*72 + rt
    int b = bi / 72, rt = bi % 72;
    int r0 = rt * 8;
    int nrows = min(8, RR - r0);
    __shared__ float sIn[C25][8][W8];
    __shared__ float sW[C25 * C25 * 3];
    __shared__ float sB[C25];
    int t = threadIdx.x;
    for (int i = t; i < C25 * C25 * 3; i += 256) sW[i] = w[i];
    if (t < C25) sB[t] = bias[t];
    for (int i = t; i < C25 * nrows * W8; i += 256) {
        int ic = i / (nrows * W8);
        int lr = (i / W8) % nrows;
        int ww = i & 7;
        sIn[ic][lr][ww] = in[(((size_t)b * C25 + ic) * RR + r0 + lr) * W8 + ww];
    }
    __syncthreads();
    if (t < 200) {
        int oc = t >> 3, ww = t & 7;
        for (int lr = 0; lr < nrows; lr++) {
            float acc = sB[oc];
            #pragma unroll
            for (int ic = 0; ic < C25; ic++) {
                const float* wp = &sW[(oc * C25 + ic) * 3];
                if (ww > 0) acc += sIn[ic][lr][ww - 1] * wp[0];
                acc += sIn[ic][lr][ww] * wp[1];
                if (ww < 7) acc += sIn[ic][lr][ww + 1] * wp[2];
            }
            out[(((size_t)b * C25 + oc) * RR + r0 + lr) * W8 + ww] = acc;
        }
    }
}

// ---------------------------------------------------------------------------
// direct 200-point real DFT magnitudes / 200 -> g_spec [T,101]
// ---------------------------------------------------------------------------
__global__ __launch_bounds__(256) void k_dft(const float* __restrict__ x) {
    int br = blockIdx.x;
    __shared__ float xs[PSZ], twc[PSZ], tws[PSZ];
    int t = threadIdx.x;
    if (t < PSZ) {
        xs[t] = x[(size_t)br * PSZ + t];
        float ang = 6.283185307179586f * (float)t / 200.f;
        twc[t] = cosf(ang);
        tws[t] = sinf(ang);
    }
    __syncthreads();
    if (t < NFREQ) {
        float re = 0.f, im = 0.f;
        int m = 0;
        #pragma unroll 8
        for (int n = 0; n < PSZ; n++) {
            re += xs[n] * twc[m];
            im += xs[n] * tws[m];
            m += t;
            if (m >= PSZ) m -= PSZ;
        }
        g_spec[(size_t)br * NFREQ + t] = sqrtf(re * re + im * im) * 0.005f;
    }
}

// reshape conv output [b,25,r,8] -> pe[t,200] (d = c*8+w), add spec_b
__global__ __launch_bounds__(256) void k_mkpe(const float* __restrict__ spec_b) {
    int i = blockIdx.x * 256 + threadIdx.x;
    if (i >= PETOT) return;
    int tkn = i / DMD, d = i % DMD;
    int b = tkn / RR, r = tkn % RR;
    g_pe[i] = g_bufA[(((size_t)b * C25 + (d >> 3)) * RR + r) * W8 + (d & 7)] + spec_b[d];
}

// ---------------------------------------------------------------------------
// generic fp32 SGEMM, 64x64 tile, BK=8, 256 threads (16x16, 4x4 micro).
// C[m,n] (+)= sum_k A[m*lda+k] * B[k*bk + n*bn]
// ---------------------------------------------------------------------------
__global__ __launch_bounds__(256) void k_sgemm(const float* __restrict__ A,
                                               const float* __restrict__ Bm,
                                               float* __restrict__ C,
                                               int M, int N, int K,
                                               int lda, int bk, int bn, int ldc,
                                               int accFlag) {
    __shared__ __align__(16) float As[8][68];
    __shared__ __align__(16) float Bs[8][68];
    int m0 = blockIdx.y * 64, n0 = blockIdx.x * 64;
    int t = threadIdx.x;
    int tx = t % 16, ty = t / 16;
    float acc[4][4];
    #pragma unroll
    for (int i = 0; i < 4; i++)
        #pragma unroll
        for (int j = 0; j < 4; j++) acc[i][j] = 0.f;

    int nk = (K + 7) / 8;
    for (int kb = 0; kb < nk; kb++) {
        int k0 = kb * 8;
        {   // A load: kk-contiguous
            int kk = t & 7, mm = t >> 3;
            int k = k0 + kk;
            #pragma unroll
            for (int hh = 0; hh < 2; hh++) {
                int m = m0 + mm + hh * 32;
                As[kk][mm + hh * 32] = (k < K && m < M) ? A[(size_t)m * lda + k] : 0.f;
            }
        }
        if (bn == 1) {  // B rows n-contiguous
            int nn = t & 63, kk4 = t >> 6;
            #pragma unroll
            for (int hh = 0; hh < 2; hh++) {
                int kk = kk4 + hh * 4;
                int k = k0 + kk, n = n0 + nn;
                Bs[kk][nn] = (k < K && n < N) ? Bm[(size_t)k * bk + n] : 0.f;
            }
        } else {        // B k-contiguous (bk==1)
            int kk = t & 7, nn = t >> 3;
            int k = k0 + kk;
            #pragma unroll
            for (int hh = 0; hh < 2; hh++) {
                int n = n0 + nn + hh * 32;
                Bs[kk][nn + hh * 32] = (k < K && n < N) ? Bm[(size_t)k * bk + (size_t)n * bn] : 0.f;
            }
        }
        __syncthreads();
        #pragma unroll
        for (int kk = 0; kk < 8; kk++) {
            float4 av = *reinterpret_cast<const float4*>(&As[kk][ty * 4]);
            float4 bv = *reinterpret_cast<const float4*>(&Bs[kk][tx * 4]);
            float a[4] = {av.x, av.y, av.z, av.w};
            float bb[4] = {bv.x, bv.y, bv.z, bv.w};
            #pragma unroll
            for (int i = 0; i < 4; i++)
                #pragma unroll
                for (int j = 0; j < 4; j++) acc[i][j] += a[i] * bb[j];
        }
        __syncthreads();
    }
    #pragma unroll
    for (int i = 0; i < 4; i++) {
        int m = m0 + ty * 4 + i;
        if (m >= M) continue;
        #pragma unroll
        for (int j = 0; j < 4; j++) {
            int n = n0 + tx * 4 + j;
            if (n < N) {
                size_t o = (size_t)m * ldc + n;
                C[o] = accFlag ? (C[o] + acc[i][j]) : acc[i][j];
            }
        }
    }
}

// c0[k] = 0.5*||cb_k||^2 - inp_b . cb_k
__global__ __launch_bounds__(256) void k_c0(const float* __restrict__ cb,
                                            const float* __restrict__ inp_b) {
    int k = blockIdx.x;
    float s = 0.f, sb = 0.f;
    for (int l = threadIdx.x; l < LLM; l += 256) {
        float v = cb[(size_t)k * LLM + l];
        s += v * v;
        sb += inp_b[l] * v;
    }
    __shared__ float r1[256], r2[256];
    int t = threadIdx.x;
    r1[t] = s; r2[t] = sb;
    __syncthreads();
    for (int st = 128; st > 0; st >>= 1) {
        if (t < st) { r1[t] += r1[t + st]; r2[t] += r2[t + st]; }
        __syncthreads();
    }
    if (t == 0) g_c0[k] = 0.5f * r1[0] - r2[0];
}

// ---------------------------------------------------------------------------
// depthwise positional conv over (19,30), kernel (19,7), pad (9,3):
// pe2 = pe + dwconv(pe) + pos_b     (pe2 written into g_bufA)
// ---------------------------------------------------------------------------
__global__ __launch_bounds__(256) void k_pos(const float* __restrict__ pw,
                                             const float* __restrict__ pb) {
    int b = blockIdx.x / DMD, d = blockIdx.x % DMD;
    __shared__ float mp[RR];
    __shared__ float w[133];
    int t = threadIdx.x;
    for (int i = t; i < RR; i += 256)
        mp[i] = g_pe[((size_t)b * RR + i) * DMD + d];
    if (t < 133) w[t] = pw[d * 133 + t];
    __syncthreads();
    float bias = pb[d];
    for (int o = t; o < RR; o += 256) {
        int ch = o / NPP, pn = o % NPP;
        float acc = mp[o] + bias;
        #pragma unroll
        for (int i = 0; i < 19; i++) {
            int ci = ch + i - 9;
            if (ci < 0 || ci >= CHN) continue;
            int base = ci * NPP;
            #pragma unroll
            for (int j = 0; j < 7; j++) {
                int pj = pn + j - 3;
                if (pj < 0 || pj >= NPP) continue;
                acc += mp[base + pj] * w[i * 7 + j];
            }
        }
        g_bufA[((size_t)b * RR + o) * DMD + d] = acc;
    }
}

// ---------------------------------------------------------------------------
// score + argmin: s[t,k] = c0[k] - pe2[t].G[k], idx[t] = argmin_k (first-min)
// M=18240 (285x64 exact), N=4096 (64x64 chunks), K=200 (25x8 exact)
// ---------------------------------------------------------------------------
__global__ __launch_bounds__(256) void k_score() {
    __shared__ __align__(16) float As[8][68];
    __shared__ __align__(16) float Bs[8][68];
    __shared__ float rv[64][17];
    __shared__ int   rix[64][17];
    int m0 = blockIdx.x * 64;
    int t = threadIdx.x;
    int tx = t % 16, ty = t / 16;
    float bestv[4];
    int besti[4];
    #pragma unroll
    for (int i = 0; i < 4; i++) { bestv[i] = INFINITY; besti[i] = 0; }

    for (int nb = 0; nb < 64; nb++) {
        int n0 = nb * 64;
        float acc[4][4];
        #pragma unroll
        for (int i = 0; i < 4; i++)
            #pragma unroll
            for (int j = 0; j < 4; j++) acc[i][j] = 0.f;
        for (int kb = 0; kb < 25; kb++) {
            int k0 = kb * 8;
            int kk = t & 7, mm = t >> 3;
            As[kk][mm]      = g_bufA[(size_t)(m0 + mm) * DMD + k0 + kk];
            As[kk][mm + 32] = g_bufA[(size_t)(m0 + mm + 32) * DMD + k0 + kk];
            Bs[kk][mm]      = g_G[(size_t)(n0 + mm) * DMD + k0 + kk];
            Bs[kk][mm + 32] = g_G[(size_t)(n0 + mm + 32) * DMD + k0 + kk];
            __syncthreads();
            #pragma unroll
            for (int kk2 = 0; kk2 < 8; kk2++) {
                float4 av = *reinterpret_cast<const float4*>(&As[kk2][ty * 4]);
                float4 bv = *reinterpret_cast<const float4*>(&Bs[kk2][tx * 4]);
                float a[4] = {av.x, av.y, av.z, av.w};
                float bb[4] = {bv.x, bv.y, bv.z, bv.w};
                #pragma unroll
                for (int i = 0; i < 4; i++)
                    #pragma unroll
                    for (int j = 0; j < 4; j++) acc[i][j] += a[i] * bb[j];
            }
            __syncthreads();
        }
        #pragma unroll
        for (int j = 0; j < 4; j++) {
            int n = n0 + tx * 4 + j;
            float cn = g_c0[n];
            #pragma unroll
            for (int i = 0; i < 4; i++) {
                float s = cn - acc[i][j];
                if (s < bestv[i]) { bestv[i] = s; besti[i] = n; }
            }
        }
    }
    #pragma unroll
    for (int i = 0; i < 4; i++) {
        rv[ty * 4 + i][tx] = bestv[i];
        rix[ty * 4 + i][tx] = besti[i];
    }
    __syncthreads();
    if (t < 64) {
        float bv = rv[t][0];
        int bi = rix[t][0];
        for (int xx = 1; xx < 16; xx++) {
            float v = rv[t][xx];
            int ii = rix[t][xx];
            if (v < bv || (v == bv && ii < bi)) { bv = v; bi = ii; }
        }
        g_idx[m0 + t] = bi;
    }
}

// out[t,d] = code_out[idx[t], d] + outp_b[d]
__global__ __launch_bounds__(256) void k_gather(const float* __restrict__ outp_b,
                                                float* __restrict__ out) {
    int i = blockIdx.x * 256 + threadIdx.x;
    if (i >= PETOT) return;
    int tkn = i / DMD, d = i % DMD;
    out[i] = g_cout[(size_t)g_idx[tkn] * DMD + d] + outp_b[d];
}

// ---------------------------------------------------------------------------
extern "C" void kernel_launch(void* const* d_in, const int* in_sizes, int n_in,
                              void* d_out, int out_size) {
    const float* x      = (const float*)d_in[0];
    const float* c1w    = (const float*)d_in[1];
    const float* c1b    = (const float*)d_in[2];
    const float* gn1s   = (const float*)d_in[3];
    const float* gn1b   = (const float*)d_in[4];
    const float* c2w    = (const float*)d_in[5];
    const float* c2b    = (const float*)d_in[6];
    const float* gn2s   = (const float*)d_in[7];
    const float* gn2b   = (const float*)d_in[8];
    const float* c3w    = (const float*)d_in[9];
    const float* c3b    = (const float*)d_in[10];
    const float* gn3s   = (const float*)d_in[11];
    const float* gn3b   = (const float*)d_in[12];
    const float* spec_w = (const float*)d_in[13];
    const float* spec_b = (const float*)d_in[14];
    const float* pos_w  = (const float*)d_in[15];
    const float* pos_b  = (const float*)d_in[16];
    const float* inp_w  = (const float*)d_in[17];
    const float* inp_b  = (const float*)d_in[18];
    const float* cb     = (const float*)d_in[19];
    const float* outp_w = (const float*)d_in[20];
    const float* outp_b = (const float*)d_in[21];
    float* out = (float*)d_out;

    float *pG, *pCout, *pSpec, *pBufA, *pBufB, *pPe;
    cudaGetSymbolAddress((void**)&pG,    g_G);
    cudaGetSymbolAddress((void**)&pCout, g_cout);
    cudaGetSymbolAddress((void**)&pSpec, g_spec);
    cudaGetSymbolAddress((void**)&pBufA, g_bufA);
    cudaGetSymbolAddress((void**)&pBufB, g_bufB);
    cudaGetSymbolAddress((void**)&pPe,   g_pe);

    const int EW = (HTOT + 255) / 256;       // elementwise grid (14250)

    // --- VQ precomputations (independent of conv chain) ---
    k_c0<<<KCB, 256>>>(cb, inp_b);
    // G = cb @ inp_w  : A=cb (lda=4096), B=inp_w (bk=200,bn=1)
    k_sgemm<<<dim3((DMD + 63) / 64, KCB / 64), 256>>>(cb, inp_w, pG,
        KCB, DMD, LLM, LLM, DMD, 1, DMD, 0);
    // code_out[k,d] = sum_l cb[k,l]*outp_w[d,l] : B=(l,d)->outp_w[d*4096+l] (bk=1,bn=4096)
    k_sgemm<<<dim3((DMD + 63) / 64, KCB / 64), 256>>>(cb, outp_w, pCout,
        KCB, DMD, LLM, LLM, 1, LLM, DMD, 0);

    // --- conv / GN / GELU chain ---
    k_conv1<<<TT, 256>>>(x, c1w, c1b);
    k_gnstats<<<BB * 5, 256>>>(pBufA);
    k_gngelu<<<EW, 256>>>(pBufA, gn1s, gn1b);
    k_conv3x<<<BB * 72, 256>>>(pBufA, c2w, c2b, pBufB);
    k_gnstats<<<BB * 5, 256>>>(pBufB);
    k_gngelu<<<EW, 256>>>(pBufB, gn2s, gn2b);
    k_conv3x<<<BB * 72, 256>>>(pBufB, c3w, c3b, pBufA);
    k_gnstats<<<BB * 5, 256>>>(pBufA);
    k_gngelu<<<EW, 256>>>(pBufA, gn3s, gn3b);

    // --- spectral branch ---
    k_dft<<<TT, 256>>>(x);
    k_mkpe<<<EW, 256>>>(spec_b);                    // pe = reshape(conv) + spec_b
    // pe += spec @ spec_w.T : A=spec (lda=101), B=(f,d)->spec_w[d*101+f] (bk=1,bn=101)
    k_sgemm<<<dim3((DMD + 63) / 64, TT / 64), 256>>>(pSpec, spec_w, pPe,
        TT, DMD, NFREQ, NFREQ, 1, NFREQ, DMD, 1);

    // --- depthwise positional conv, pe2 -> g_bufA ---
    k_pos<<<BB * DMD, 256>>>(pos_w, pos_b);

    // --- fused score GEMM + argmin ---
    k_score<<<TT / 64, 256>>>();

    // --- output gather ---
    k_gather<<<EW, 256>>>(outp_b, out);
}

// round 3
// speedup vs baseline: 1.2463x; 1.2463x over previous
#include <cuda_runtime.h>
#include <cuda_bf16.h>
#include <math.h>

// ---------------------------------------------------------------------------
// CSBrainLLMVQ: EEG conv stack + GN + GELU + DFT spectral branch + depthwise
// positional conv + VQ (argmin over codebook) + output projection.
//
// Restructuring (exact math, fp32 throughout):
//   score[t,k] = 0.5*||cb_k||^2 - inp_b.cb_k - pe2[t].G[k],  G = cb @ inp_w
//   out[t]     = code_out[idx[t]] + outp_b,   code_out = cb @ outp_w.T
// GEMM inner loops use packed fp32 FMA (fma.rn.f32x2) -> 2 FMA/instr.
// NOTE: GN-apply expression must stay bit-identical to the R1 formulation:
//   v = (raw - mean) * rstd * scale + bias   (no gA/gB refactor!)
// because the VQ argmin has ~1e-6-level top-2 gaps for a few tokens.
// ---------------------------------------------------------------------------

#define BB   32
#define CHN  19
#define NPP  30
#define PSZ  200
#define RR   570          // CHN*NPP
#define TT   18240        // BB*RR
#define DMD  200
#define LLM  4096
#define KCB  4096
#define C25  25
#define W8   8
#define HTOT (BB*C25*RR*W8)   // 3,648,000
#define PETOT (TT*DMD)        // 3,648,000
#define NFREQ 101

// scratch (device globals: no allocation allowed)
__device__ float g_bufA[HTOT];
__device__ float g_bufB[HTOT];
__device__ float g_pe[PETOT];
__device__ float g_spec[TT*NFREQ];
__device__ float g_G[KCB*DMD];
__device__ float g_c0[KCB];
__device__ float g_cout[KCB*DMD];
__device__ int   g_idx[TT];
__device__ float g_mean[BB*5];
__device__ float g_rstd[BB*5];

__device__ __forceinline__ float gelu_exact(float v) {
    return 0.5f * v * (1.0f + erff(v * 0.70710678118654752f));
}

#define PACKDUP(dst, a) \
    asm("mov.b64 %0, {%1, %1};" : "=l"(dst) : "r"(__float_as_uint(a)))
#define PACK2(dst, a, b) \
    asm("mov.b64 %0, {%1, %2};" : "=l"(dst) : "r"(__float_as_uint(a)), "r"(__float_as_uint(b)))
#define FMA2(acc, a, b) \
    asm("fma.rn.f32x2 %0, %1, %2, %0;" : "+l"(acc) : "l"(a), "l"(b))
#define UNPK2(lo, hi, v) \
    asm("mov.b64 {%0, %1}, %2;" : "=r"(lo), "=r"(hi) : "l"(v))

// ---------------------------------------------------------------------------
// conv1: [B,1,570,200] -> [B,25,570,8], kernel (1,49), stride (1,25), pad W 24
// ---------------------------------------------------------------------------
__global__ __launch_bounds__(256) void k_conv1(const float* __restrict__ x,
                                               const float* __restrict__ w,
                                               const float* __restrict__ bias) {
    int br = blockIdx.x;                 // b*570 + r
    int b = br / RR, r = br % RR;
    __shared__ float xs[PSZ];
    __shared__ float ws[C25 * 49];
    __shared__ float bs[C25];
    int t = threadIdx.x;
    if (t < PSZ) xs[t] = x[(size_t)br * PSZ + t];
    for (int i = t; i < C25 * 49; i += 256) ws[i] = w[i];
    if (t < C25) bs[t] = bias[t];
    __syncthreads();
    if (t < 200) {
        int oc = t >> 3, ow = t & 7;
        float acc = bs[oc];
        int base = ow * 25 - 24;
        #pragma unroll 7
        for (int k = 0; k < 49; k++) {
            int p = base + k;
            if (p >= 0 && p < PSZ) acc += xs[p] * ws[oc * 49 + k];
        }
        g_bufA[(((size_t)b * C25 + oc) * RR + r) * W8 + ow] = acc;
    }
}

// ---------------------------------------------------------------------------
// GroupNorm stats on RAW conv output: 5 groups of 5 channels
// ---------------------------------------------------------------------------
__global__ __launch_bounds__(256) void k_gnstats(const float* __restrict__ h) {
    int bg = blockIdx.x;           // b*5 + g
    int b = bg / 5, g = bg % 5;
    float s1 = 0.f, s2 = 0.f;
    const int per = RR * W8;       // 4560
    for (int i = threadIdx.x; i < 5 * per; i += 256) {
        int oc = g * 5 + i / per;
        int rw = i % per;
        float v = h[(size_t)(b * C25 + oc) * per + rw];
        s1 += v; s2 += v * v;
    }
    __shared__ float r1[256], r2[256];
    int t = threadIdx.x;
    r1[t] = s1; r2[t] = s2;
    __syncthreads();
    for (int s = 128; s > 0; s >>= 1) {
        if (t < s) { r1[t] += r1[t + s]; r2[t] += r2[t + s]; }
        __syncthreads();
    }
    if (t == 0) {
        float m = r1[0] / 22800.f;
        float var = r2[0] / 22800.f - m * m;
        g_mean[bg] = m;
        g_rstd[bg] = rsqrtf(var + 1e-5f);
    }
}

// ---------------------------------------------------------------------------
// conv2/conv3 with fused GN-apply + GELU on the INPUT (raw -> normalized):
// out_raw = conv( gelu(gn(in_raw)) )
// GN expression matches R1's k_gngelu bit-exactly.
// ---------------------------------------------------------------------------
__global__ __launch_bounds__(256) void k_conv3x(const float* __restrict__ in,
                                                const float* __restrict__ w,
                                                const float* __restrict__ bias,
                                                const float* __restrict__ gns,
                                                const float* __restrict__ gnb,
                                                float* __restrict__ out) {
    int bi = blockIdx.x;                // b*72 + rt
    int b = bi / 72, rt = bi % 72;
    int r0 = rt * 8;
    int nrows = min(8, RR - r0);
    __shared__ float sIn[C25][8][W8];
    __shared__ float sW[C25 * C25 * 3];
    __shared__ float sB[C25];
    __shared__ float sMean[C25], sRstd[C25], sSc[C25], sBi[C25];
    int t = threadIdx.x;
    for (int i = t; i < C25 * C25 * 3; i += 256) sW[i] = w[i];
    if (t < C25) {
        sB[t] = bias[t];
        int bg = b * 5 + t / 5;
        sMean[t] = g_mean[bg];
        sRstd[t] = g_rstd[bg];
        sSc[t]   = gns[t];
        sBi[t]   = gnb[t];
    }
    for (int i = t; i < C25 * nrows * W8; i += 256) {
        int ic = i / (nrows * W8);
        int lr = (i / W8) % nrows;
        int ww = i & 7;
        sIn[ic][lr][ww] = in[(((size_t)b * C25 + ic) * RR + r0 + lr) * W8 + ww];
    }
    __syncthreads();
    // in-place GN + GELU transform (R1-exact expression)
    for (int i = t; i < C25 * nrows * W8; i += 256) {
        int ic = i / (nrows * W8);
        int lr = (i / W8) % nrows;
        int ww = i & 7;
        float v = (sIn[ic][lr][ww] - sMean[ic]) * sRstd[ic] * sSc[ic] + sBi[ic];
        sIn[ic][lr][ww] = gelu_exact(v);
    }
    __syncthreads();
    if (t < 200) {
        int oc = t >> 3, ww = t & 7;
        for (int lr = 0; lr < nrows; lr++) {
            float acc = sB[oc];
            #pragma unroll
            for (int ic = 0; ic < C25; ic++) {
                const float* wp = &sW[(oc * C25 + ic) * 3];
                if (ww > 0) acc += sIn[ic][lr][ww - 1] * wp[0];
                acc += sIn[ic][lr][ww] * wp[1];
                if (ww < 7) acc += sIn[ic][lr][ww + 1] * wp[2];
            }
            out[(((size_t)b * C25 + oc) * RR + r0 + lr) * W8 + ww] = acc;
        }
    }
}

// ---------------------------------------------------------------------------
// direct 200-point real DFT magnitudes / 200 -> g_spec [T,101]; 2 tokens/block
// ---------------------------------------------------------------------------
__global__ __launch_bounds__(256) void k_dft(const float* __restrict__ x) {
    __shared__ float xs[2][PSZ], twc[PSZ], tws[PSZ];
    int t = threadIdx.x;
    const float* xp = x + (size_t)blockIdx.x * (2 * PSZ);
    for (int i = t; i < 2 * PSZ; i += 256) ((float*)xs)[i] = xp[i];
    if (t < PSZ) {
        float ang = 6.283185307179586f * (float)t / 200.f;
        twc[t] = cosf(ang);
        tws[t] = sinf(ang);
    }
    __syncthreads();
    if (t < 2 * NFREQ) {
        int tok = t / NFREQ, f = t % NFREQ;
        const float* xv = xs[tok];
        float re = 0.f, im = 0.f;
        int m = 0;
        #pragma unroll 8
        for (int n = 0; n < PSZ; n++) {
            re += xv[n] * twc[m];
            im += xv[n] * tws[m];
            m += f;
            if (m >= PSZ) m -= PSZ;
        }
        g_spec[((size_t)blockIdx.x * 2 + tok) * NFREQ + f] = sqrtf(re * re + im * im) * 0.005f;
    }
}

// pe[t,d] = gelu(gn3(conv3_raw)) reshaped + spec_b[d]   (R1-exact GN expr)
__global__ __launch_bounds__(256) void k_mkpe(const float* __restrict__ gns,
                                              const float* __restrict__ gnb,
                                              const float* __restrict__ spec_b) {
    int i = blockIdx.x * 256 + threadIdx.x;
    if (i >= PETOT) return;
    int tkn = i / DMD, d = i % DMD;
    int b = tkn / RR, r = tkn % RR;
    int ic = d >> 3;
    int bg = b * 5 + ic / 5;
    float raw = g_bufA[(((size_t)b * C25 + ic) * RR + r) * W8 + (d & 7)];
    float v = (raw - g_mean[bg]) * g_rstd[bg] * gns[ic] + gnb[ic];
    g_pe[i] = gelu_exact(v) + spec_b[d];
}

// ---------------------------------------------------------------------------
// generic fp32 SGEMM (used only for the small spectral projection)
// C[m,n] (+)= sum_k A[m*lda+k] * B[k*bk + n*bn]
// ---------------------------------------------------------------------------
__global__ __launch_bounds__(256) void k_sgemm(const float* __restrict__ A,
                                               const float* __restrict__ Bm,
                                               float* __restrict__ C,
                                               int M, int N, int K,
                                               int lda, int bk, int bn, int ldc,
                                               int accFlag) {
    __shared__ __align__(16) float As[8][68];
    __shared__ __align__(16) float Bs[8][68];
    int m0 = blockIdx.y * 64, n0 = blockIdx.x * 64;
    int t = threadIdx.x;
    int tx = t % 16, ty = t / 16;
    float acc[4][4];
    #pragma unroll
    for (int i = 0; i < 4; i++)
        #pragma unroll
        for (int j = 0; j < 4; j++) acc[i][j] = 0.f;

    int nk = (K + 7) / 8;
    for (int kb = 0; kb < nk; kb++) {
        int k0 = kb * 8;
        {
            int kk = t & 7, mm = t >> 3;
            int k = k0 + kk;
            #pragma unroll
            for (int hh = 0; hh < 2; hh++) {
                int m = m0 + mm + hh * 32;
                As[kk][mm + hh * 32] = (k < K && m < M) ? A[(size_t)m * lda + k] : 0.f;
            }
        }
        {
            int kk = t & 7, nn = t >> 3;
            int k = k0 + kk;
            #pragma unroll
            for (int hh = 0; hh < 2; hh++) {
                int n = n0 + nn + hh * 32;
                Bs[kk][nn + hh * 32] = (k < K && n < N) ? Bm[(size_t)k * bk + (size_t)n * bn] : 0.f;
            }
        }
        __syncthreads();
        #pragma unroll
        for (int kk = 0; kk < 8; kk++) {
            float4 av = *reinterpret_cast<const float4*>(&As[kk][ty * 4]);
            float4 bv = *reinterpret_cast<const float4*>(&Bs[kk][tx * 4]);
            float a[4] = {av.x, av.y, av.z, av.w};
            float bb[4] = {bv.x, bv.y, bv.z, bv.w};
            #pragma unroll
            for (int i = 0; i < 4; i++)
                #pragma unroll
                for (int j = 0; j < 4; j++) acc[i][j] += a[i] * bb[j];
        }
        __syncthreads();
    }
    #pragma unroll
    for (int i = 0; i < 4; i++) {
        int m = m0 + ty * 4 + i;
        if (m >= M) continue;
        #pragma unroll
        for (int j = 0; j < 4; j++) {
            int n = n0 + tx * 4 + j;
            if (n < N) {
                size_t o = (size_t)m * ldc + n;
                C[o] = accFlag ? (C[o] + acc[i][j]) : acc[i][j];
            }
        }
    }
}

// c0[k] = 0.5*||cb_k||^2 - inp_b . cb_k
__global__ __launch_bounds__(256) void k_c0(const float* __restrict__ cb,
                                            const float* __restrict__ inp_b) {
    int k = blockIdx.x;
    float s = 0.f, sb = 0.f;
    for (int l = threadIdx.x; l < LLM; l += 256) {
        float v = cb[(size_t)k * LLM + l];
        s += v * v;
        sb += inp_b[l] * v;
    }
    __shared__ float r1[256], r2[256];
    int t = threadIdx.x;
    r1[t] = s; r2[t] = sb;
    __syncthreads();
    for (int st = 128; st > 0; st >>= 1) {
        if (t < st) { r1[t] += r1[t + st]; r2[t] += r2[t + st]; }
        __syncthreads();
    }
    if (t == 0) g_c0[k] = 0.5f * r1[0] - r2[0];
}

// ---------------------------------------------------------------------------
// k_prep: dual GEMM sharing A-tile (cb):
//   G[m,n]    = sum_k cb[m,k] * inp_w[k,n]       (inp_w [4096,200], n-contig)
//   cout[m,n] = sum_k cb[m,k] * outp_w[n,k]      (outp_w [200,4096], k-contig)
// M=4096, N=200, K=4096. Tile 64x64, micro 4x4, FMA2.
// ---------------------------------------------------------------------------
__global__ __launch_bounds__(256) void k_prep(const float* __restrict__ cb,
                                              const float* __restrict__ inp_w,
                                              const float* __restrict__ outp_w) {
    __shared__ __align__(16) float As[2][8][68];
    __shared__ __align__(16) float B1s[2][8][68];
    __shared__ __align__(16) float B2s[2][8][68];
    const int t = threadIdx.x;
    const int tx = t & 15, ty = t >> 4;
    const int lk = t & 7, lm = t >> 3;       // 8 x 32
    const int nn = t & 63, kq = t >> 6;      // 64 x 4
    const int m0 = blockIdx.y * 64, n0 = blockIdx.x * 64;

    unsigned long long a1[4][2], a2[4][2];
    #pragma unroll
    for (int i = 0; i < 4; i++)
        #pragma unroll
        for (int jp = 0; jp < 2; jp++) { a1[i][jp] = 0ULL; a2[i][jp] = 0ULL; }

    // prologue: tile 0
    #pragma unroll
    for (int h = 0; h < 2; h++) {
        As[0][lk][lm + h * 32] = cb[(size_t)(m0 + lm + h * 32) * LLM + lk];
        int kk = kq + h * 4;
        B1s[0][kk][nn] = (n0 + nn < DMD) ? inp_w[(size_t)kk * DMD + n0 + nn] : 0.f;
        B2s[0][lk][lm + h * 32] = (n0 + lm + h * 32 < DMD)
            ? outp_w[(size_t)(n0 + lm + h * 32) * LLM + lk] : 0.f;
    }
    __syncthreads();
    for (int kb = 0; kb < LLM / 8; kb++) {
        int cur = kb & 1, nxt = cur ^ 1;
        if (kb < LLM / 8 - 1) {
            int k0 = (kb + 1) * 8;
            #pragma unroll
            for (int h = 0; h < 2; h++) {
                As[nxt][lk][lm + h * 32] = cb[(size_t)(m0 + lm + h * 32) * LLM + k0 + lk];
                int kk = kq + h * 4;
                B1s[nxt][kk][nn] = (n0 + nn < DMD) ? inp_w[(size_t)(k0 + kk) * DMD + n0 + nn] : 0.f;
                B2s[nxt][lk][lm + h * 32] = (n0 + lm + h * 32 < DMD)
                    ? outp_w[(size_t)(n0 + lm + h * 32) * LLM + k0 + lk] : 0.f;
            }
        }
        #pragma unroll
        for (int kk = 0; kk < 8; kk++) {
            float4 av = *reinterpret_cast<const float4*>(&As[cur][kk][ty * 4]);
            float4 b1 = *reinterpret_cast<const float4*>(&B1s[cur][kk][tx * 4]);
            float4 b2 = *reinterpret_cast<const float4*>(&B2s[cur][kk][tx * 4]);
            unsigned long long b1p[2], b2p[2];
            PACK2(b1p[0], b1.x, b1.y); PACK2(b1p[1], b1.z, b1.w);
            PACK2(b2p[0], b2.x, b2.y); PACK2(b2p[1], b2.z, b2.w);
            float aa[4] = {av.x, av.y, av.z, av.w};
            #pragma unroll
            for (int i = 0; i < 4; i++) {
                unsigned long long ap;
                PACKDUP(ap, aa[i]);
                FMA2(a1[i][0], ap, b1p[0]);
                FMA2(a1[i][1], ap, b1p[1]);
                FMA2(a2[i][0], ap, b2p[0]);
                FMA2(a2[i][1], ap, b2p[1]);
            }
        }
        __syncthreads();
    }
    // epilogue
    #pragma unroll
    for (int i = 0; i < 4; i++) {
        int m = m0 + ty * 4 + i;
        #pragma unroll
        for (int jp = 0; jp < 2; jp++) {
            unsigned lo, hi;
            int n = n0 + tx * 4 + jp * 2;
            UNPK2(lo, hi, a1[i][jp]);
            if (n < DMD)     g_G[(size_t)m * DMD + n]     = __uint_as_float(lo);
            if (n + 1 < DMD) g_G[(size_t)m * DMD + n + 1] = __uint_as_float(hi);
            UNPK2(lo, hi, a2[i][jp]);
            if (n < DMD)     g_cout[(size_t)m * DMD + n]     = __uint_as_float(lo);
            if (n + 1 < DMD) g_cout[(size_t)m * DMD + n + 1] = __uint_as_float(hi);
        }
    }
}

// ---------------------------------------------------------------------------
// depthwise positional conv over (19,30), kernel (19,7), pad (9,3):
// pe2 = pe + dwconv(pe) + pos_b     (pe2 written into g_bufA)
// ---------------------------------------------------------------------------
__global__ __launch_bounds__(256) void k_pos(const float* __restrict__ pw,
                                             const float* __restrict__ pb) {
    int b = blockIdx.x / DMD, d = blockIdx.x % DMD;
    __shared__ float mp[RR];
    __shared__ float w[133];
    int t = threadIdx.x;
    for (int i = t; i < RR; i += 256)
        mp[i] = g_pe[((size_t)b * RR + i) * DMD + d];
    if (t < 133) w[t] = pw[d * 133 + t];
    __syncthreads();
    float bias = pb[d];
    for (int o = t; o < RR; o += 256) {
        int ch = o / NPP, pn = o % NPP;
        float acc = mp[o] + bias;
        #pragma unroll
        for (int i = 0; i < 19; i++) {
            int ci = ch + i - 9;
            if (ci < 0 || ci >= CHN) continue;
            int base = ci * NPP;
            #pragma unroll
            for (int j = 0; j < 7; j++) {
                int pj = pn + j - 3;
                if (pj < 0 || pj >= NPP) continue;
                acc += mp[base + pj] * w[i * 7 + j];
            }
        }
        g_bufA[((size_t)b * RR + o) * DMD + d] = acc;
    }
}

// ---------------------------------------------------------------------------
// score + argmin: s[t,k] = c0[k] - pe2[t].G[k], idx[t] = argmin_k (first-min)
// M=18240 (285x64 exact), N=4096 (32 tiles of 128), K=200 (25x8 exact)
// Tile 64x128, micro 4x8, FMA2 accumulators, fused running argmin.
// ---------------------------------------------------------------------------
__global__ __launch_bounds__(256) void k_score2() {
    __shared__ __align__(16) float As[2][8][68];
    __shared__ __align__(16) float Bs[2][8][136];
    __shared__ float cs[128];
    __shared__ float rv[64][17];
    __shared__ int   rix[64][17];
    const int t = threadIdx.x;
    const int tx = t & 15, ty = t >> 4;
    const int lk = t & 7, lm = t >> 3;
    const int m0 = blockIdx.x * 64;
    float bestv[4]; int besti[4];
    #pragma unroll
    for (int i = 0; i < 4; i++) { bestv[i] = INFINITY; besti[i] = 0; }

    for (int nb = 0; nb < 32; nb++) {
        const int n0 = nb * 128;
        __syncthreads();   // protects cs + smem reuse vs previous epilogue
        if (t < 128) cs[t] = g_c0[n0 + t];
        unsigned long long accp[4][4];
        #pragma unroll
        for (int i = 0; i < 4; i++)
            #pragma unroll
            for (int jp = 0; jp < 4; jp++) accp[i][jp] = 0ULL;
        // prologue tile 0
        #pragma unroll
        for (int h = 0; h < 2; h++)
            As[0][lk][lm + h * 32] = g_bufA[(size_t)(m0 + lm + h * 32) * DMD + lk];
        #pragma unroll
        for (int h = 0; h < 4; h++)
            Bs[0][lk][lm + h * 32] = g_G[(size_t)(n0 + lm + h * 32) * DMD + lk];
        __syncthreads();
        for (int kb = 0; kb < 25; kb++) {
            int cur = kb & 1, nxt = cur ^ 1;
            if (kb < 24) {
                int k = (kb + 1) * 8 + lk;
                #pragma unroll
                for (int h = 0; h < 2; h++)
                    As[nxt][lk][lm + h * 32] = g_bufA[(size_t)(m0 + lm + h * 32) * DMD + k];
                #pragma unroll
                for (int h = 0; h < 4; h++)
                    Bs[nxt][lk][lm + h * 32] = g_G[(size_t)(n0 + lm + h * 32) * DMD + k];
            }
            #pragma unroll
            for (int kk = 0; kk < 8; kk++) {
                float4 av = *reinterpret_cast<const float4*>(&As[cur][kk][ty * 4]);
                float4 b0 = *reinterpret_cast<const float4*>(&Bs[cur][kk][tx * 8]);
                float4 b1 = *reinterpret_cast<const float4*>(&Bs[cur][kk][tx * 8 + 4]);
                unsigned long long bp[4];
                PACK2(bp[0], b0.x, b0.y); PACK2(bp[1], b0.z, b0.w);
                PACK2(bp[2], b1.x, b1.y); PACK2(bp[3], b1.z, b1.w);
                float aa[4] = {av.x, av.y, av.z, av.w};
                #pragma unroll
                for (int i = 0; i < 4; i++) {
                    unsigned long long ap;
                    PACKDUP(ap, aa[i]);
                    FMA2(accp[i][0], ap, bp[0]);
                    FMA2(accp[i][1], ap, bp[1]);
                    FMA2(accp[i][2], ap, bp[2]);
                    FMA2(accp[i][3], ap, bp[3]);
                }
            }
            __syncthreads();
        }
        // running argmin epilogue (ascending n for first-min tie-break)
        #pragma unroll
        for (int jp = 0; jp < 4; jp++) {
            int nl = tx * 8 + jp * 2;
            float c0v = cs[nl], c1v = cs[nl + 1];
            #pragma unroll
            for (int i = 0; i < 4; i++) {
                unsigned lo, hi;
                UNPK2(lo, hi, accp[i][jp]);
                float s0 = c0v - __uint_as_float(lo);
                float s1 = c1v - __uint_as_float(hi);
                if (s0 < bestv[i]) { bestv[i] = s0; besti[i] = n0 + nl; }
                if (s1 < bestv[i]) { bestv[i] = s1; besti[i] = n0 + nl + 1; }
            }
        }
    }
    #pragma unroll
    for (int i = 0; i < 4; i++) { rv[ty * 4 + i][tx] = bestv[i]; rix[ty * 4 + i][tx] = besti[i]; }
    __syncthreads();
    if (t < 64) {
        float bv = rv[t][0]; int bi_ = rix[t][0];
        for (int xx = 1; xx < 16; xx++) {
            float v = rv[t][xx]; int ii = rix[t][xx];
            if (v < bv || (v == bv && ii < bi_)) { bv = v; bi_ = ii; }
        }
        g_idx[m0 + t] = bi_;
    }
}

// out[t,d] = code_out[idx[t], d] + outp_b[d]
__global__ __launch_bounds__(256) void k_gather(const float* __restrict__ outp_b,
                                                float* __restrict__ out) {
    int i = blockIdx.x * 256 + threadIdx.x;
    if (i >= PETOT) return;
    int tkn = i / DMD, d = i % DMD;
    out[i] = g_cout[(size_t)g_idx[tkn] * DMD + d] + outp_b[d];
}

// ---------------------------------------------------------------------------
extern "C" void kernel_launch(void* const* d_in, const int* in_sizes, int n_in,
                              void* d_out, int out_size) {
    const float* x      = (const float*)d_in[0];
    const float* c1w    = (const float*)d_in[1];
    const float* c1b    = (const float*)d_in[2];
    const float* gn1s   = (const float*)d_in[3];
    const float* gn1b   = (const float*)d_in[4];
    const float* c2w    = (const float*)d_in[5];
    const float* c2b    = (const float*)d_in[6];
    const float* gn2s   = (const float*)d_in[7];
    const float* gn2b   = (const float*)d_in[8];
    const float* c3w    = (const float*)d_in[9];
    const float* c3b    = (const float*)d_in[10];
    const float* gn3s   = (const float*)d_in[11];
    const float* gn3b   = (const float*)d_in[12];
    const float* spec_w = (const float*)d_in[13];
    const float* spec_b = (const float*)d_in[14];
    const float* pos_w  = (const float*)d_in[15];
    const float* pos_b  = (const float*)d_in[16];
    const float* inp_w  = (const float*)d_in[17];
    const float* inp_b  = (const float*)d_in[18];
    const float* cb     = (const float*)d_in[19];
    const float* outp_w = (const float*)d_in[20];
    const float* outp_b = (const float*)d_in[21];
    float* out = (float*)d_out;

    float *pSpec, *pBufA, *pBufB, *pPe;
    cudaGetSymbolAddress((void**)&pSpec, g_spec);
    cudaGetSymbolAddress((void**)&pBufA, g_bufA);
    cudaGetSymbolAddress((void**)&pBufB, g_bufB);
    cudaGetSymbolAddress((void**)&pPe,   g_pe);

    const int EW = (HTOT + 255) / 256;       // 14250

    // --- VQ precomputations ---
    k_prep<<<dim3(4, 64), 256>>>(cb, inp_w, outp_w);
    k_c0<<<KCB, 256>>>(cb, inp_b);

    // --- conv / GN / GELU chain (GN-apply+GELU fused into consumers) ---
    k_conv1<<<TT, 256>>>(x, c1w, c1b);
    k_gnstats<<<BB * 5, 256>>>(pBufA);
    k_conv3x<<<BB * 72, 256>>>(pBufA, c2w, c2b, gn1s, gn1b, pBufB);
    k_gnstats<<<BB * 5, 256>>>(pBufB);
    k_conv3x<<<BB * 72, 256>>>(pBufB, c3w, c3b, gn2s, gn2b, pBufA);
    k_gnstats<<<BB * 5, 256>>>(pBufA);

    // --- spectral branch ---
    k_dft<<<TT / 2, 256>>>(x);
    k_mkpe<<<EW, 256>>>(gn3s, gn3b, spec_b);    // pe = gelu(gn3(conv3)) + spec_b
    // pe += spec @ spec_w.T : B=(f,d)->spec_w[d*101+f] (bk=1,bn=101)
    k_sgemm<<<dim3((DMD + 63) / 64, TT / 64), 256>>>(pSpec, spec_w, pPe,
        TT, DMD, NFREQ, NFREQ, 1, NFREQ, DMD, 1);

    // --- depthwise positional conv, pe2 -> g_bufA ---
    k_pos<<<BB * DMD, 256>>>(pos_w, pos_b);

    // --- fused score GEMM + argmin (FMA2) ---
    k_score2<<<TT / 64, 256>>>();

    // --- output gather ---
    k_gather<<<EW, 256>>>(outp_b, out);
}